// round 1
// baseline (speedup 1.0000x reference)
#include <cuda_runtime.h>
#include <cuda_bf16.h>
#include <math_constants.h>

// Shapes fixed by the problem
#define BB 16
#define NP 8192
#define NG 128
#define NC 80
#define TPB 256
#define BPB (NP / TPB)          // 32 blocks per batch
#define NBLK (BB * BPB)         // 512 blocks total

// Per-block partials: [sum_ciou_w, sum_ce_w, n_match, penalty, sum_bce_w, n_valid]
__device__ float g_partials[NBLK * 8];

__global__ __launch_bounds__(TPB)
void yolo_main(const float4* __restrict__ y_hat,   // (B,NP,4) xywh
               const float4* __restrict__ y_gt,    // (B,NG,4) xywh
               const float*  __restrict__ obj,     // (B,NP)
               const float4* __restrict__ cls_pred,// (B,NP,NC)
               const int*    __restrict__ cls_tgt, // (B,NG)
               const int*    __restrict__ min_score)
{
    __shared__ float4 s_g[NG];    // gt xyxy
    __shared__ float  s_ga[NG];   // gt area
    __shared__ float  s_gw[NG];   // small-obj weight (2.0 or 1.0)
    __shared__ int    s_gt[NG];   // gt class
    __shared__ float  s_red[8][6];

    const int b = blockIdx.x / BPB;
    const int p = (blockIdx.x % BPB) * TPB + threadIdx.x;

    if (threadIdx.x < NG) {
        float4 g = y_gt[b * NG + threadIdx.x];
        float x1 = g.x - g.z * 0.5f, y1 = g.y - g.w * 0.5f;
        float x2 = g.x + g.z * 0.5f, y2 = g.y + g.w * 0.5f;
        s_g[threadIdx.x]  = make_float4(x1, y1, x2, y2);
        s_ga[threadIdx.x] = (x2 - x1) * (y2 - y1);
        s_gw[threadIdx.x] = (g.z < 0.05f || g.w < 0.05f) ? 2.0f : 1.0f;
        s_gt[threadIdx.x] = cls_tgt[b * NG + threadIdx.x];
    }
    __syncthreads();

    // Prediction box (xyxy) and area
    float4 pb = y_hat[b * NP + p];
    const float px1 = pb.x - pb.z * 0.5f, py1 = pb.y - pb.w * 0.5f;
    const float px2 = pb.x + pb.z * 0.5f, py2 = pb.y + pb.w * 0.5f;
    const float pa  = (px2 - px1) * (py2 - py1);

    const float s   = obj[b * NP + p];
    const float thr = (float)min_score[0];   // 0 has identical bits as int or f32
    const bool  valid = s > thr;

    // Division-free argmax of inter/union over GTs (first-occurrence semantics)
    float best_i = -1.0f, best_u = 1.0f;
    int   best_idx = 0;
    #pragma unroll 4
    for (int g = 0; g < NG; ++g) {
        float4 gb = s_g[g];
        float iw = fminf(px2, gb.z) - fmaxf(px1, gb.x);
        float ih = fminf(py2, gb.w) - fmaxf(py1, gb.y);
        iw = fmaxf(iw, 0.0f);
        ih = fmaxf(ih, 0.0f);
        float inter = iw * ih;
        float uni   = pa + s_ga[g] - inter;     // reference iou_mat has no eps
        if (inter * best_u > best_i * uni) {    // strict > keeps first max index
            best_i = inter; best_u = uni; best_idx = g;
        }
    }
    const bool matched = valid && (2.0f * best_i > best_u);  // max_iou > 0.5

    float acc[6] = {0.f, 0.f, 0.f, 0.f, 0.f, 0.f};
    if (valid) {
        acc[5] = 1.0f;                                  // n_valid
        const float lbl = matched ? 1.0f : 0.0f;
        float bce = fmaxf(s, 0.0f) - s * lbl + log1pf(expf(-fabsf(s)));
        float wobj = (matched && s < 0.5f) ? 2.0f : 1.0f;
        acc[4] = bce * wobj;                            // sum_bce_w

        if (matched) {
            acc[2] = 1.0f;                              // n_match
            const float eps = 1e-7f;
            float4 gb = s_g[best_idx];
            float ws  = s_gw[best_idx];

            // CIoU (with eps, per reference _bbox_ciou)
            float b2a = (gb.z - gb.x) * (gb.w - gb.y);
            float iw = fmaxf(fminf(px2, gb.z) - fmaxf(px1, gb.x), 0.0f);
            float ih = fmaxf(fminf(py2, gb.w) - fmaxf(py1, gb.y), 0.0f);
            float inter = iw * ih;
            float uni   = pa + b2a - inter + eps;
            float iou   = inter / uni;
            float cw = fmaxf(px2, gb.z) - fminf(px1, gb.x);
            float ch = fmaxf(py2, gb.w) - fminf(py1, gb.y);
            float c2 = cw * cw + ch * ch + eps;
            float dx = (px1 + px2) * 0.5f - (gb.x + gb.z) * 0.5f;
            float dy = (py1 + py2) * 0.5f - (gb.y + gb.w) * 0.5f;
            float d2 = dx * dx + dy * dy;
            float w1 = px2 - px1, h1 = py2 - py1;
            float w2 = gb.z - gb.x, h2 = gb.w - gb.y;
            float dat = atanf(w1 / (h1 + eps)) - atanf(w2 / (h2 + eps));
            float v = (4.0f / (CUDART_PI_F * CUDART_PI_F)) * dat * dat;
            float alpha = v / (1.0f - iou + v + eps);
            float ciou = iou - (d2 / c2 + alpha * v);
            acc[0] = (1.0f - ciou) * ws;                // sum_ciou_w

            // Cross-entropy: lse - x[tgt] over this row only (two passes, L1 reuse)
            const float4* row = cls_pred + (size_t)(b * NP + p) * (NC / 4);
            float m = -CUDART_INF_F;
            #pragma unroll
            for (int i = 0; i < NC / 4; ++i) {
                float4 v4 = row[i];
                m = fmaxf(m, fmaxf(fmaxf(v4.x, v4.y), fmaxf(v4.z, v4.w)));
            }
            float se = 0.0f;
            #pragma unroll
            for (int i = 0; i < NC / 4; ++i) {
                float4 v4 = row[i];
                se += __expf(v4.x - m) + __expf(v4.y - m) +
                      __expf(v4.z - m) + __expf(v4.w - m);
            }
            float lse = m + __logf(se);
            float xt  = ((const float*)row)[s_gt[best_idx]];
            acc[1] = (lse - xt) * ws;                   // sum_ce_w
        } else {
            acc[3] = 0.1f * s;                          // penalty
        }
    }

    // Deterministic block reduction of 6 values
    const int lane = threadIdx.x & 31, warp = threadIdx.x >> 5;
    #pragma unroll
    for (int k = 0; k < 6; ++k) {
        float x = acc[k];
        #pragma unroll
        for (int o = 16; o; o >>= 1) x += __shfl_xor_sync(0xFFFFFFFFu, x, o);
        if (lane == 0) s_red[warp][k] = x;
    }
    __syncthreads();
    if (warp == 0) {
        #pragma unroll
        for (int k = 0; k < 6; ++k) {
            float x = (lane < 8) ? s_red[lane][k] : 0.0f;
            #pragma unroll
            for (int o = 4; o; o >>= 1) x += __shfl_xor_sync(0xFFFFFFFFu, x, o);
            if (lane == 0) g_partials[blockIdx.x * 8 + k] = x;
        }
    }
}

// 1 block, 512 threads: warp w reduces batch w's 32 block-partials, then
// thread 0 combines the 16 per-batch losses into the scalar.
__global__ __launch_bounds__(512)
void yolo_final(float* __restrict__ out)
{
    const int warp = threadIdx.x >> 5;   // batch index (16 warps)
    const int lane = threadIdx.x & 31;   // block-partial index (32 per batch)
    const float* src = g_partials + (warp * BPB + lane) * 8;

    float v[6];
    #pragma unroll
    for (int k = 0; k < 6; ++k) {
        float x = src[k];
        #pragma unroll
        for (int o = 16; o; o >>= 1) x += __shfl_xor_sync(0xFFFFFFFFu, x, o);
        v[k] = x;
    }

    __shared__ float pb[BB];
    __shared__ float vb[BB];
    if (lane == 0) {
        float sum_ciou = v[0], sum_ce = v[1], nm = v[2];
        float pen = v[3], sum_bce = v[4], nv = v[5];
        float loc = (nm > 0.f) ? sum_ciou / nm : 0.0f;
        float cls = (nm > 0.f) ? sum_ce   / nm : 0.0f;
        float ob  = (nv > 0.f) ? sum_bce  / nv : 0.0f;
        pb[warp] = 5.0f * loc + 1.0f * ob + pen + cls;
        vb[warp] = (nv > 0.f) ? 1.0f : 0.0f;
    }
    __syncthreads();
    if (threadIdx.x == 0) {
        float sum = 0.f, cnt = 0.f;
        #pragma unroll
        for (int i = 0; i < BB; ++i) { sum += vb[i] * pb[i]; cnt += vb[i]; }
        out[0] = sum / fmaxf(cnt, 1.0f);
    }
}

extern "C" void kernel_launch(void* const* d_in, const int* in_sizes, int n_in,
                              void* d_out, int out_size)
{
    const float4* y_hat    = (const float4*)d_in[0];
    const float4* y_gt     = (const float4*)d_in[1];
    const float*  obj      = (const float*) d_in[2];
    const float4* cls_pred = (const float4*)d_in[3];
    const int*    cls_tgt  = (const int*)   d_in[4];
    const int*    min_sc   = (const int*)   d_in[5];
    float* out = (float*)d_out;

    yolo_main<<<NBLK, TPB>>>(y_hat, y_gt, obj, cls_pred, cls_tgt, min_sc);
    yolo_final<<<1, 512>>>(out);
}

// round 2
// speedup vs baseline: 1.0816x; 1.0816x over previous
#include <cuda_runtime.h>
#include <cuda_bf16.h>
#include <math_constants.h>

// Shapes fixed by the problem
#define BB 16
#define NP 8192
#define NG 128
#define NC 80
#define TPB 256
#define PPT 2                          // predictions per thread
#define PREDS_PER_BLK (TPB * PPT)      // 512
#define BPB (NP / PREDS_PER_BLK)       // 16 blocks per batch
#define NBLK (BB * BPB)                // 256 blocks total

// Per-block partials: [sum_ciou_w, sum_ce_w, n_match, penalty, sum_bce_w, n_valid]
__device__ float    g_partials[NBLK * 8];
__device__ unsigned g_count;           // zero-initialized; reset by last block each launch

__device__ __forceinline__ void pred_epilogue(
    float px1, float py1, float px2, float py2, float pa,
    float s, bool valid, unsigned best,
    const float4* s_g, const float* s_ga, const float* s_gw, const int* s_gt,
    const float4* __restrict__ cls_row,   // row pointer for this prediction
    float acc[6])
{
    const int gbest = 127 - (int)(best & 127u);
    const float4 gb = s_g[gbest];

    // Exact max_iou at the winning index (reference iou_mat: no eps)
    float iw = fmaxf(fminf(px2, gb.z) - fmaxf(px1, gb.x), 0.0f);
    float ih = fmaxf(fminf(py2, gb.w) - fmaxf(py1, gb.y), 0.0f);
    float inter = iw * ih;
    float ga = s_ga[gbest];
    float max_iou = inter / (pa + ga - inter);
    const bool matched = valid && (max_iou > 0.5f);

    if (!valid) return;
    acc[5] += 1.0f;                                        // n_valid
    const float lbl = matched ? 1.0f : 0.0f;
    float bce = fmaxf(s, 0.0f) - s * lbl + log1pf(expf(-fabsf(s)));
    acc[4] += (matched && s < 0.5f) ? 2.0f * bce : bce;    // sum_bce_w

    if (matched) {
        acc[2] += 1.0f;                                    // n_match
        const float eps = 1e-7f;
        const float ws = s_gw[gbest];

        // CIoU (with eps, per reference _bbox_ciou)
        float uni_e = pa + ga - inter + eps;
        float iou   = inter / uni_e;
        float cw = fmaxf(px2, gb.z) - fminf(px1, gb.x);
        float ch = fmaxf(py2, gb.w) - fminf(py1, gb.y);
        float c2 = cw * cw + ch * ch + eps;
        float dx = (px1 + px2) * 0.5f - (gb.x + gb.z) * 0.5f;
        float dy = (py1 + py2) * 0.5f - (gb.y + gb.w) * 0.5f;
        float d2 = dx * dx + dy * dy;
        float w1 = px2 - px1, h1 = py2 - py1;
        float w2 = gb.z - gb.x, h2 = gb.w - gb.y;
        float dat = atanf(w1 / (h1 + eps)) - atanf(w2 / (h2 + eps));
        float v = (4.0f / (CUDART_PI_F * CUDART_PI_F)) * dat * dat;
        float alpha = v / (1.0f - iou + v + eps);
        float ciou = iou - (d2 / c2 + alpha * v);
        acc[0] += (1.0f - ciou) * ws;                      // sum_ciou_w

        // Cross-entropy over this row only (320B, two passes, second hits L1)
        float m = -CUDART_INF_F;
        #pragma unroll
        for (int i = 0; i < NC / 4; ++i) {
            float4 v4 = cls_row[i];
            m = fmaxf(m, fmaxf(fmaxf(v4.x, v4.y), fmaxf(v4.z, v4.w)));
        }
        float se = 0.0f;
        #pragma unroll
        for (int i = 0; i < NC / 4; ++i) {
            float4 v4 = cls_row[i];
            se += __expf(v4.x - m) + __expf(v4.y - m) +
                  __expf(v4.z - m) + __expf(v4.w - m);
        }
        float lse = m + __logf(se);
        float xt  = ((const float*)cls_row)[s_gt[gbest]];
        acc[1] += (lse - xt) * ws;                         // sum_ce_w
    } else {
        acc[3] += 0.1f * s;                                // penalty
    }
}

__global__ __launch_bounds__(TPB)
void yolo_fused(const float4* __restrict__ y_hat,   // (B,NP,4) xywh
                const float4* __restrict__ y_gt,    // (B,NG,4) xywh
                const float*  __restrict__ obj,     // (B,NP)
                const float4* __restrict__ cls_pred,// (B,NP,NC)
                const int*    __restrict__ cls_tgt, // (B,NG)
                const int*    __restrict__ min_score,
                float* __restrict__ out)
{
    __shared__ float4 s_g[NG];
    __shared__ float  s_ga[NG];
    __shared__ float  s_gw[NG];
    __shared__ int    s_gt[NG];
    __shared__ float  s_red[8][6];
    __shared__ unsigned s_old;

    const int b    = blockIdx.x / BPB;
    const int tile = blockIdx.x % BPB;
    const int base = b * NP + tile * PREDS_PER_BLK;
    const int t    = threadIdx.x;

    if (t < NG) {
        float4 g = y_gt[b * NG + t];
        float x1 = g.x - g.z * 0.5f, y1 = g.y - g.w * 0.5f;
        float x2 = g.x + g.z * 0.5f, y2 = g.y + g.w * 0.5f;
        s_g[t]  = make_float4(x1, y1, x2, y2);
        s_ga[t] = (x2 - x1) * (y2 - y1);
        s_gw[t] = (g.z < 0.05f || g.w < 0.05f) ? 2.0f : 1.0f;
        s_gt[t] = cls_tgt[b * NG + t];
    }
    __syncthreads();

    // Two predictions per thread (coalesced)
    const int pA = base + t;
    const int pB = base + t + TPB;
    float4 ha = y_hat[pA], hb = y_hat[pB];
    const float ax1 = ha.x - ha.z * 0.5f, ay1 = ha.y - ha.w * 0.5f;
    const float ax2 = ha.x + ha.z * 0.5f, ay2 = ha.y + ha.w * 0.5f;
    const float paA = (ax2 - ax1) * (ay2 - ay1);
    const float bx1 = hb.x - hb.z * 0.5f, by1 = hb.y - hb.w * 0.5f;
    const float bx2 = hb.x + hb.z * 0.5f, by2 = hb.y + hb.w * 0.5f;
    const float paB = (bx2 - bx1) * (by2 - by1);

    const float sA = obj[pA], sB = obj[pB];
    const float thr = (float)min_score[0];

    // Division-free-latency argmax: pack index into low 7 bits of iou bits.
    // Positive-float bit order == value order; 127-g tie-breaks to first index.
    unsigned bestA = 0u, bestB = 0u;
    #pragma unroll 4
    for (int g = 0; g < NG; ++g) {
        float4 gb = s_g[g];
        float ga = s_ga[g];
        unsigned tie = (unsigned)(127 - g);
        {
            float iw = fminf(ax2, gb.z) - fmaxf(ax1, gb.x);
            float ih = fminf(ay2, gb.w) - fmaxf(ay1, gb.y);
            float inter = fmaxf(iw, 0.0f) * fmaxf(ih, 0.0f);
            float uni = paA + ga - inter;
            float iou = __fdividef(inter, uni);
            unsigned key = (__float_as_uint(iou) & 0xFFFFFF80u) | tie;
            bestA = bestA > key ? bestA : key;
        }
        {
            float iw = fminf(bx2, gb.z) - fmaxf(bx1, gb.x);
            float ih = fminf(by2, gb.w) - fmaxf(by1, gb.y);
            float inter = fmaxf(iw, 0.0f) * fmaxf(ih, 0.0f);
            float uni = paB + ga - inter;
            float iou = __fdividef(inter, uni);
            unsigned key = (__float_as_uint(iou) & 0xFFFFFF80u) | tie;
            bestB = bestB > key ? bestB : key;
        }
    }

    float acc[6] = {0.f, 0.f, 0.f, 0.f, 0.f, 0.f};
    pred_epilogue(ax1, ay1, ax2, ay2, paA, sA, sA > thr, bestA,
                  s_g, s_ga, s_gw, s_gt,
                  cls_pred + (size_t)pA * (NC / 4), acc);
    pred_epilogue(bx1, by1, bx2, by2, paB, sB, sB > thr, bestB,
                  s_g, s_ga, s_gw, s_gt,
                  cls_pred + (size_t)pB * (NC / 4), acc);

    // Deterministic block reduction of 6 values
    const int lane = t & 31, warp = t >> 5;
    #pragma unroll
    for (int k = 0; k < 6; ++k) {
        float x = acc[k];
        #pragma unroll
        for (int o = 16; o; o >>= 1) x += __shfl_xor_sync(0xFFFFFFFFu, x, o);
        if (lane == 0) s_red[warp][k] = x;
    }
    __syncthreads();
    if (t == 0) {
        #pragma unroll
        for (int k = 0; k < 6; ++k) {
            float x = 0.0f;
            #pragma unroll
            for (int w = 0; w < 8; ++w) x += s_red[w][k];
            g_partials[blockIdx.x * 8 + k] = x;
        }
        __threadfence();
        s_old = atomicAdd(&g_count, 1u);
    }
    __syncthreads();

    // Last block performs the final reduction (deterministic order)
    if (s_old == NBLK - 1) {
        __threadfence();
        __shared__ float s_loss[BB], s_vb[BB];
        if (t < BB) {
            float a0 = 0, a1 = 0, a2 = 0, a3 = 0, a4 = 0, a5 = 0;
            #pragma unroll
            for (int j = 0; j < BPB; ++j) {
                const float* q = g_partials + (t * BPB + j) * 8;
                a0 += q[0]; a1 += q[1]; a2 += q[2];
                a3 += q[3]; a4 += q[4]; a5 += q[5];
            }
            float loc = (a2 > 0.f) ? a0 / a2 : 0.0f;
            float cls = (a2 > 0.f) ? a1 / a2 : 0.0f;
            float ob  = (a5 > 0.f) ? a4 / a5 : 0.0f;
            s_loss[t] = 5.0f * loc + ob + a3 + cls;
            s_vb[t]   = (a5 > 0.f) ? 1.0f : 0.0f;
        }
        __syncthreads();
        if (t == 0) {
            float sum = 0.f, cnt = 0.f;
            #pragma unroll
            for (int i = 0; i < BB; ++i) { sum += s_vb[i] * s_loss[i]; cnt += s_vb[i]; }
            out[0] = sum / fmaxf(cnt, 1.0f);
            g_count = 0u;   // reset for next graph replay
        }
    }
}

extern "C" void kernel_launch(void* const* d_in, const int* in_sizes, int n_in,
                              void* d_out, int out_size)
{
    const float4* y_hat    = (const float4*)d_in[0];
    const float4* y_gt     = (const float4*)d_in[1];
    const float*  obj      = (const float*) d_in[2];
    const float4* cls_pred = (const float4*)d_in[3];
    const int*    cls_tgt  = (const int*)   d_in[4];
    const int*    min_sc   = (const int*)   d_in[5];
    float* out = (float*)d_out;

    yolo_fused<<<NBLK, TPB>>>(y_hat, y_gt, obj, cls_pred, cls_tgt, min_sc, out);
}